// round 1
// baseline (speedup 1.0000x reference)
#include <cuda_runtime.h>
#include <cuda_bf16.h>
#include <math.h>

#define NNODES 50000
#define KNEI   32
#define DIM    128
#define DOUT   128

// Scratch for aggregated neighbor means (static device arrays: allowed).
__device__ float g_nei1[(size_t)NNODES * DIM];
__device__ float g_nei2[(size_t)NNODES * DIM];

// ---------------------------------------------------------------------------
// Kernel 1: neighbor mean aggregation. One warp per node, both lists.
// Each lane owns one float4 (4 contiguous cols) of the 128-float row.
// Indices are lane-loaded once and broadcast via shfl; the 32-deep loop is
// fully unrolled -> 32 independent LDG.128 in flight per list (high MLP).
// ---------------------------------------------------------------------------
__global__ void agg_kernel(const float* __restrict__ fea1,
                           const int*   __restrict__ idx1,
                           const int*   __restrict__ idx2) {
    int gwarp = (blockIdx.x * blockDim.x + threadIdx.x) >> 5;
    int lane  = threadIdx.x & 31;
    if (gwarp >= NNODES) return;

    const float4* f4 = reinterpret_cast<const float4*>(fea1);

    // ---- list 1 ----
    {
        int myidx = idx1[gwarp * KNEI + lane];
        float4 acc = make_float4(0.f, 0.f, 0.f, 0.f);
        #pragma unroll
        for (int j = 0; j < KNEI; j++) {
            int id = __shfl_sync(0xffffffffu, myidx, j);
            float4 v = __ldg(&f4[(size_t)id * (DIM / 4) + lane]);
            acc.x += v.x; acc.y += v.y; acc.z += v.z; acc.w += v.w;
        }
        const float s = 1.0f / (float)KNEI;
        float4 m = make_float4(acc.x * s, acc.y * s, acc.z * s, acc.w * s);
        reinterpret_cast<float4*>(g_nei1)[(size_t)gwarp * (DIM / 4) + lane] = m;
    }
    // ---- list 2 ----
    {
        int myidx = idx2[gwarp * KNEI + lane];
        float4 acc = make_float4(0.f, 0.f, 0.f, 0.f);
        #pragma unroll
        for (int j = 0; j < KNEI; j++) {
            int id = __shfl_sync(0xffffffffu, myidx, j);
            float4 v = __ldg(&f4[(size_t)id * (DIM / 4) + lane]);
            acc.x += v.x; acc.y += v.y; acc.z += v.z; acc.w += v.w;
        }
        const float s = 1.0f / (float)KNEI;
        float4 m = make_float4(acc.x * s, acc.y * s, acc.z * s, acc.w * s);
        reinterpret_cast<float4*>(g_nei2)[(size_t)gwarp * (DIM / 4) + lane] = m;
    }
}

// ---------------------------------------------------------------------------
// Kernel 2: out = tanh( [fea1 | fea2 | nei1 | nei2] @ W ),  W: [512, 128]
// Classic fp32 SGEMM tiling: BM=128, BN=128, BK=16, 256 threads, 8x8
// register micro-tile per thread. The virtual 512-wide A matrix is read via
// a 4-entry source-pointer table (each 16-wide k-tile lies in one source).
// ---------------------------------------------------------------------------
#define BM 128
#define BN 128
#define BK 16
#define TM 8
#define TN 8

__global__ __launch_bounds__(256, 2)
void gemm_tanh_kernel(const float* __restrict__ fea1,
                      const float* __restrict__ fea2,
                      const float* __restrict__ W,
                      float* __restrict__ out) {
    __shared__ float As[BK][BM];       // transposed A tile
    __shared__ float Bs[BK][BN];

    const int block_row = blockIdx.x * BM;
    const int tid = threadIdx.x;
    const int tx  = tid & 15;          // 0..15 -> output col group
    const int ty  = tid >> 4;          // 0..15 -> output row group

    const float* srcs[4] = {fea1, fea2, g_nei1, g_nei2};

    float acc[TM][TN];
    #pragma unroll
    for (int i = 0; i < TM; i++)
        #pragma unroll
        for (int j = 0; j < TN; j++)
            acc[i][j] = 0.f;

    #pragma unroll 1
    for (int kt = 0; kt < (4 * DIM) / BK; kt++) {     // 32 k-tiles
        const int   ksrc = kt >> 3;                   // 8 tiles per source
        const int   kcol = (kt & 7) * BK;             // col offset in source
        const float* A   = srcs[ksrc];

        // ---- load A tile (128 x 16) as float4, store transposed ----
        #pragma unroll
        for (int u = 0; u < 2; u++) {
            int unit = tid + u * 256;                 // 0..511
            int r    = unit >> 2;                     // 0..127
            int c4   = unit & 3;                      // 0..3
            int gr   = block_row + r;
            float4 v = make_float4(0.f, 0.f, 0.f, 0.f);
            if (gr < NNODES)
                v = *reinterpret_cast<const float4*>(A + (size_t)gr * DIM + kcol + c4 * 4);
            As[c4 * 4 + 0][r] = v.x;
            As[c4 * 4 + 1][r] = v.y;
            As[c4 * 4 + 2][r] = v.z;
            As[c4 * 4 + 3][r] = v.w;
        }
        // ---- load B tile (16 x 128) as float4 ----
        #pragma unroll
        for (int u = 0; u < 2; u++) {
            int unit = tid + u * 256;                 // 0..511
            int r    = unit >> 5;                     // 0..15
            int c4   = unit & 31;                     // 0..31
            float4 v = *reinterpret_cast<const float4*>(
                W + (size_t)(kt * BK + r) * DOUT + c4 * 4);
            *reinterpret_cast<float4*>(&Bs[r][c4 * 4]) = v;
        }
        __syncthreads();

        // ---- 8x8 micro-tile FMA ----
        #pragma unroll
        for (int kk = 0; kk < BK; kk++) {
            float a[TM], b[TN];
            #pragma unroll
            for (int i = 0; i < TM; i += 4)
                *reinterpret_cast<float4*>(&a[i]) =
                    *reinterpret_cast<const float4*>(&As[kk][ty * TM + i]);
            #pragma unroll
            for (int j = 0; j < TN; j += 4)
                *reinterpret_cast<float4*>(&b[j]) =
                    *reinterpret_cast<const float4*>(&Bs[kk][tx * TN + j]);
            #pragma unroll
            for (int i = 0; i < TM; i++)
                #pragma unroll
                for (int j = 0; j < TN; j++)
                    acc[i][j] = fmaf(a[i], b[j], acc[i][j]);
        }
        __syncthreads();
    }

    // ---- epilogue: tanh + store ----
    #pragma unroll
    for (int i = 0; i < TM; i++) {
        int gr = block_row + ty * TM + i;
        if (gr < NNODES) {
            #pragma unroll
            for (int j = 0; j < TN; j += 4) {
                float4 v;
                v.x = tanhf(acc[i][j + 0]);
                v.y = tanhf(acc[i][j + 1]);
                v.z = tanhf(acc[i][j + 2]);
                v.w = tanhf(acc[i][j + 3]);
                *reinterpret_cast<float4*>(out + (size_t)gr * DOUT + tx * TN + j) = v;
            }
        }
    }
}

extern "C" void kernel_launch(void* const* d_in, const int* in_sizes, int n_in,
                              void* d_out, int out_size) {
    const float* node_fea1 = (const float*)d_in[0];
    const float* node_fea2 = (const float*)d_in[1];
    const int*   neigh1    = (const int*)  d_in[2];
    const int*   neigh2    = (const int*)  d_in[3];
    const float* weight    = (const float*)d_in[4];
    float*       out       = (float*)d_out;

    // Kernel 1: aggregation (8 warps/block -> 6250 blocks)
    {
        int warps_per_block = 8;
        int blocks = (NNODES + warps_per_block - 1) / warps_per_block;
        agg_kernel<<<blocks, warps_per_block * 32>>>(node_fea1, neigh1, neigh2);
    }
    // Kernel 2: fused concat-GEMM + tanh
    {
        int blocks = (NNODES + BM - 1) / BM;   // 391
        gemm_tanh_kernel<<<blocks, 256>>>(node_fea1, node_fea2, weight, out);
    }
}

// round 3
// speedup vs baseline: 1.5776x; 1.5776x over previous
#include <cuda_runtime.h>
#include <cuda_bf16.h>
#include <math.h>
#include <stdint.h>

#define NNODES 50000
#define KNEI   32
#define DIM    128
#define DOUT   128
#define KTOT   512          // 4*DIM
#define BM     128
#define BK     32
#define SASTR  36           // padded smem row stride (floats) -> conflict-free frags

// Scratch (static device arrays: allowed).
__device__ float    g_nei1[(size_t)NNODES * DIM];
__device__ float    g_nei2[(size_t)NNODES * DIM];
__device__ uint32_t g_WT[(size_t)DOUT * KTOT];   // WT[n][k] = tf32rn(W[k][n])

__device__ __forceinline__ uint32_t f2tf32(float f) {
    uint32_t u;
    asm("cvt.rna.tf32.f32 %0, %1;" : "=r"(u) : "f"(f));
    return u;
}

// m16n8k8 tf32 mma, fp32 accumulate (sm_80+ baseline feature)
__device__ __forceinline__ void mma_tf32(float c[4], const uint32_t a[4],
                                         const uint32_t b[2]) {
    asm volatile(
        "mma.sync.aligned.m16n8k8.row.col.f32.tf32.tf32.f32 "
        "{%0,%1,%2,%3}, {%4,%5,%6,%7}, {%8,%9}, {%0,%1,%2,%3};"
        : "+f"(c[0]), "+f"(c[1]), "+f"(c[2]), "+f"(c[3])
        : "r"(a[0]), "r"(a[1]), "r"(a[2]), "r"(a[3]), "r"(b[0]), "r"(b[1]));
}

// ---------------------------------------------------------------------------
// Kernel 0: transpose W [512,128] -> WT [128,512], tf32-RN rounded.
// ---------------------------------------------------------------------------
__global__ void wt_kernel(const float* __restrict__ W) {
    int idx = blockIdx.x * blockDim.x + threadIdx.x;
    if (idx >= KTOT * DOUT) return;
    int n = idx / KTOT;
    int k = idx % KTOT;
    g_WT[(size_t)n * KTOT + k] = f2tf32(W[(size_t)k * DOUT + n]);
}

// ---------------------------------------------------------------------------
// Kernel 1: neighbor mean aggregation (one warp per node, both lists).
// ---------------------------------------------------------------------------
__global__ void agg_kernel(const float* __restrict__ fea1,
                           const int*   __restrict__ idx1,
                           const int*   __restrict__ idx2) {
    int gwarp = (blockIdx.x * blockDim.x + threadIdx.x) >> 5;
    int lane  = threadIdx.x & 31;
    if (gwarp >= NNODES) return;

    const float4* f4 = reinterpret_cast<const float4*>(fea1);
    {
        int myidx = idx1[gwarp * KNEI + lane];
        float4 acc = make_float4(0.f, 0.f, 0.f, 0.f);
        #pragma unroll
        for (int j = 0; j < KNEI; j++) {
            int id = __shfl_sync(0xffffffffu, myidx, j);
            float4 v = __ldg(&f4[(size_t)id * (DIM / 4) + lane]);
            acc.x += v.x; acc.y += v.y; acc.z += v.z; acc.w += v.w;
        }
        const float s = 1.0f / (float)KNEI;
        reinterpret_cast<float4*>(g_nei1)[(size_t)gwarp * (DIM / 4) + lane] =
            make_float4(acc.x * s, acc.y * s, acc.z * s, acc.w * s);
    }
    {
        int myidx = idx2[gwarp * KNEI + lane];
        float4 acc = make_float4(0.f, 0.f, 0.f, 0.f);
        #pragma unroll
        for (int j = 0; j < KNEI; j++) {
            int id = __shfl_sync(0xffffffffu, myidx, j);
            float4 v = __ldg(&f4[(size_t)id * (DIM / 4) + lane]);
            acc.x += v.x; acc.y += v.y; acc.z += v.z; acc.w += v.w;
        }
        const float s = 1.0f / (float)KNEI;
        reinterpret_cast<float4*>(g_nei2)[(size_t)gwarp * (DIM / 4) + lane] =
            make_float4(acc.x * s, acc.y * s, acc.z * s, acc.w * s);
    }
}

// ---------------------------------------------------------------------------
// Kernel 2: tf32 mma.sync GEMM + tanh.
// out = tanh([fea1|fea2|nei1|nei2] @ W).  BM=128, BN=128, BK=32.
// 8 warps: 2 (M) x 4 (N); each warp does 64x32 via 4x4 m16n8k8 tiles.
// ---------------------------------------------------------------------------
__global__ __launch_bounds__(256, 2)
void gemm_mma_kernel(const float* __restrict__ fea1,
                     const float* __restrict__ fea2,
                     float* __restrict__ out) {
    __shared__ uint32_t sA[BM * SASTR];    // [m][k], tf32 bits, stride 36
    __shared__ uint32_t sB[DOUT * SASTR];  // [n][k], tf32 bits, stride 36

    const int tid  = threadIdx.x;
    const int wid  = tid >> 5;
    const int lane = tid & 31;
    const int gid  = lane >> 2;      // 0..7
    const int tig  = lane & 3;       // 0..3
    const int warp_m = (wid >> 2) * 64;   // 0 or 64
    const int warp_n = (wid & 3) * 32;    // 0,32,64,96
    const int block_row = blockIdx.x * BM;

    const float* srcs[4] = {fea1, fea2, g_nei1, g_nei2};

    float acc[4][4][4];
    #pragma unroll
    for (int mt = 0; mt < 4; mt++)
        #pragma unroll
        for (int nt = 0; nt < 4; nt++)
            #pragma unroll
            for (int i = 0; i < 4; i++)
                acc[mt][nt][i] = 0.f;

    #pragma unroll 1
    for (int kc = 0; kc < KTOT / BK; kc++) {   // 16 chunks
        const float* A  = srcs[kc >> 2];
        const int   colb = (kc & 3) * BK;

        // ---- stage A: 128 rows x 32 k (tf32-converted), 4 uint4 per thread
        #pragma unroll
        for (int i = 0; i < 4; i++) {
            int u = tid + i * 256;         // 0..1023
            int r = u >> 3;                // 0..127
            int c = (u & 7) * 4;           // 0,4,..28
            int gr = block_row + r;
            if (gr >= NNODES) gr = NNODES - 1;   // clamp; rows masked at store
            float4 v = *reinterpret_cast<const float4*>(A + (size_t)gr * DIM + colb + c);
            uint4 t;
            t.x = f2tf32(v.x); t.y = f2tf32(v.y);
            t.z = f2tf32(v.z); t.w = f2tf32(v.w);
            *reinterpret_cast<uint4*>(&sA[r * SASTR + c]) = t;
        }
        // ---- stage B: 128 n-rows x 32 k (already tf32 in g_WT)
        #pragma unroll
        for (int i = 0; i < 4; i++) {
            int u = tid + i * 256;
            int r = u >> 3;
            int c = (u & 7) * 4;
            uint4 v = *reinterpret_cast<const uint4*>(g_WT + (size_t)r * KTOT + kc * BK + c);
            *reinterpret_cast<uint4*>(&sB[r * SASTR + c]) = v;
        }
        __syncthreads();

        // ---- 4 k-steps of k8 ----
        #pragma unroll
        for (int ks = 0; ks < 4; ks++) {
            const int ko = ks * 8;
            uint32_t af[4][4];
            #pragma unroll
            for (int mt = 0; mt < 4; mt++) {
                int row = warp_m + mt * 16 + gid;
                af[mt][0] = sA[row * SASTR + ko + tig];
                af[mt][1] = sA[(row + 8) * SASTR + ko + tig];
                af[mt][2] = sA[row * SASTR + ko + tig + 4];
                af[mt][3] = sA[(row + 8) * SASTR + ko + tig + 4];
            }
            uint32_t bf[4][2];
            #pragma unroll
            for (int nt = 0; nt < 4; nt++) {
                int col = warp_n + nt * 8 + gid;
                bf[nt][0] = sB[col * SASTR + ko + tig];
                bf[nt][1] = sB[col * SASTR + ko + tig + 4];
            }
            #pragma unroll
            for (int mt = 0; mt < 4; mt++)
                #pragma unroll
                for (int nt = 0; nt < 4; nt++)
                    mma_tf32(acc[mt][nt], af[mt], bf[nt]);
        }
        __syncthreads();
    }

    // ---- epilogue: tanh + store (c0,c1)=(row,2tig..), (c2,c3)=(row+8,..) ----
    #pragma unroll
    for (int mt = 0; mt < 4; mt++) {
        #pragma unroll
        for (int half = 0; half < 2; half++) {
            int gr = block_row + warp_m + mt * 16 + gid + half * 8;
            if (gr < NNODES) {
                #pragma unroll
                for (int nt = 0; nt < 4; nt++) {
                    float2 v;
                    v.x = tanhf(acc[mt][nt][half * 2 + 0]);
                    v.y = tanhf(acc[mt][nt][half * 2 + 1]);
                    *reinterpret_cast<float2*>(
                        out + (size_t)gr * DOUT + warp_n + nt * 8 + tig * 2) = v;
                }
            }
        }
    }
}

// ---------------------------------------------------------------------------
extern "C" void kernel_launch(void* const* d_in, const int* in_sizes, int n_in,
                              void* d_out, int out_size) {
    const float* node_fea1 = (const float*)d_in[0];
    const float* node_fea2 = (const float*)d_in[1];
    const int*   neigh1    = (const int*)  d_in[2];
    const int*   neigh2    = (const int*)  d_in[3];
    const float* weight    = (const float*)d_in[4];
    float*       out       = (float*)d_out;

    wt_kernel<<<(KTOT * DOUT + 255) / 256, 256>>>(weight);

    {
        int warps_per_block = 8;
        int blocks = (NNODES + warps_per_block - 1) / warps_per_block;
        agg_kernel<<<blocks, warps_per_block * 32>>>(node_fea1, neigh1, neigh2);
    }
    {
        int blocks = (NNODES + BM - 1) / BM;   // 391
        gemm_mma_kernel<<<blocks, 256>>>(node_fea1, node_fea2, out);
    }
}

// round 4
// speedup vs baseline: 2.1950x; 1.3913x over previous
#include <cuda_runtime.h>
#include <cuda_bf16.h>
#include <math.h>
#include <stdint.h>

#define NNODES 50000
#define KNEI   32
#define DIM    128
#define DOUT   128
#define KTOT   512           // 4*DIM
#define BM     128
#define BK     32
#define SSTR   36             // padded smem row stride (u32) -> conflict-free LDS

// Static device scratch (allowed).
__device__ uint32_t g_f1t [(size_t)NNODES * DIM];   // tf32(fea1)
__device__ uint32_t g_f2t [(size_t)NNODES * DIM];   // tf32(fea2)
__device__ uint32_t g_n1t [(size_t)NNODES * DIM];   // tf32(mean nei1)
__device__ uint32_t g_n2t [(size_t)NNODES * DIM];   // tf32(mean nei2)
__device__ uint32_t g_WT  [(size_t)DOUT * KTOT];    // WT[n][k] = tf32(W[k][n])

__device__ __forceinline__ uint32_t f2tf32(float f) {
    uint32_t u;
    asm("cvt.rna.tf32.f32 %0, %1;" : "=r"(u) : "f"(f));
    return u;
}
__device__ __forceinline__ uint32_t smem_u32(const void* p) {
    uint32_t a;
    asm("{ .reg .u64 t; cvta.to.shared.u64 t, %1; cvt.u32.u64 %0, t; }" : "=r"(a) : "l"(p));
    return a;
}
__device__ __forceinline__ void cp_async16(uint32_t dst, const void* src) {
    asm volatile("cp.async.cg.shared.global [%0], [%1], 16;"
                 :: "r"(dst), "l"(src) : "memory");
}
#define CP_COMMIT() asm volatile("cp.async.commit_group;" ::: "memory")
#define CP_WAIT0()  asm volatile("cp.async.wait_group 0;"  ::: "memory")

// m16n8k8 tf32 mma, fp32 accumulate (sm_80+ baseline)
__device__ __forceinline__ void mma_tf32(float c[4], const uint32_t a[4],
                                         const uint32_t b[2]) {
    asm volatile(
        "mma.sync.aligned.m16n8k8.row.col.f32.tf32.tf32.f32 "
        "{%0,%1,%2,%3}, {%4,%5,%6,%7}, {%8,%9}, {%0,%1,%2,%3};"
        : "+f"(c[0]), "+f"(c[1]), "+f"(c[2]), "+f"(c[3])
        : "r"(a[0]), "r"(a[1]), "r"(a[2]), "r"(a[3]), "r"(b[0]), "r"(b[1]));
}

// ---------------------------------------------------------------------------
// Kernel 1 (prep): per block (6250 blocks x 256 threads):
//   - convert a 1024-elem slice of fea1 & fea2 to tf32 bits
//   - blocks < 256: transpose+convert a 256-elem slice of W
//   - aggregate 8 nodes (one warp each), write means as tf32 bits
// ---------------------------------------------------------------------------
__global__ __launch_bounds__(256)
void prep_kernel(const float* __restrict__ fea1,
                 const float* __restrict__ fea2,
                 const int*   __restrict__ idx1,
                 const int*   __restrict__ idx2,
                 const float* __restrict__ W) {
    const int b    = blockIdx.x;
    const int tid  = threadIdx.x;
    const int lane = tid & 31;

    // ---- fea1/fea2 tf32 conversion: 1 float4 per thread per array ----
    {
        size_t p = (size_t)b * 256 + tid;   // float4 index, 6250*256 = 1.6M = exact
        float4 v1 = reinterpret_cast<const float4*>(fea1)[p];
        float4 v2 = reinterpret_cast<const float4*>(fea2)[p];
        uint4 t1, t2;
        t1.x = f2tf32(v1.x); t1.y = f2tf32(v1.y); t1.z = f2tf32(v1.z); t1.w = f2tf32(v1.w);
        t2.x = f2tf32(v2.x); t2.y = f2tf32(v2.y); t2.z = f2tf32(v2.z); t2.w = f2tf32(v2.w);
        reinterpret_cast<uint4*>(g_f1t)[p] = t1;
        reinterpret_cast<uint4*>(g_f2t)[p] = t2;
    }
    // ---- W transpose (+tf32): blocks 0..255, 256 elems each ----
    if (b < 256) {
        int id = b * 256 + tid;            // 0..65535
        int k  = id >> 7;                  // 0..511
        int n  = id & 127;                 // coalesced read of W[k][*]
        g_WT[(size_t)n * KTOT + k] = f2tf32(W[(size_t)k * DOUT + n]);
    }
    // ---- aggregation: one warp per node ----
    const int node = b * 8 + (tid >> 5);   // < 50000 exactly
    const float4* f4 = reinterpret_cast<const float4*>(fea1);
    const float s = 1.0f / (float)KNEI;
    {
        int myidx = idx1[node * KNEI + lane];
        float4 acc = make_float4(0.f, 0.f, 0.f, 0.f);
        #pragma unroll
        for (int j = 0; j < KNEI; j++) {
            int id = __shfl_sync(0xffffffffu, myidx, j);
            float4 v = __ldg(&f4[(size_t)id * (DIM / 4) + lane]);
            acc.x += v.x; acc.y += v.y; acc.z += v.z; acc.w += v.w;
        }
        uint4 t;
        t.x = f2tf32(acc.x * s); t.y = f2tf32(acc.y * s);
        t.z = f2tf32(acc.z * s); t.w = f2tf32(acc.w * s);
        reinterpret_cast<uint4*>(g_n1t)[(size_t)node * (DIM / 4) + lane] = t;
    }
    {
        int myidx = idx2[node * KNEI + lane];
        float4 acc = make_float4(0.f, 0.f, 0.f, 0.f);
        #pragma unroll
        for (int j = 0; j < KNEI; j++) {
            int id = __shfl_sync(0xffffffffu, myidx, j);
            float4 v = __ldg(&f4[(size_t)id * (DIM / 4) + lane]);
            acc.x += v.x; acc.y += v.y; acc.z += v.z; acc.w += v.w;
        }
        uint4 t;
        t.x = f2tf32(acc.x * s); t.y = f2tf32(acc.y * s);
        t.z = f2tf32(acc.z * s); t.w = f2tf32(acc.w * s);
        reinterpret_cast<uint4*>(g_n2t)[(size_t)node * (DIM / 4) + lane] = t;
    }
}

// ---------------------------------------------------------------------------
// Kernel 2: tf32 mma GEMM + tanh, 2-stage cp.async ping-pong.
// out = tanh([f1|f2|n1|n2] @ W).  BM=128, BN=128, BK=32, 8 warps 2x4,
// each warp 64x32 via 4x4 m16n8k8 tiles.
// Dynamic smem: 2 stages x (A 128x36 + B 128x36) u32 = 73728 B.
// ---------------------------------------------------------------------------
#define STAGE_U32 (2 * BM * SSTR)   // per-stage A+B (9216 u32)

__global__ __launch_bounds__(256, 2)
void gemm_mma_kernel(float* __restrict__ out) {
    extern __shared__ uint32_t smem[];

    const int tid  = threadIdx.x;
    const int wid  = tid >> 5;
    const int lane = tid & 31;
    const int gid  = lane >> 2;            // 0..7
    const int tig  = lane & 3;             // 0..3
    const int warp_m = (wid >> 2) * 64;    // 0 / 64
    const int warp_n = (wid & 3) * 32;     // 0,32,64,96
    const int block_row = blockIdx.x * BM;

    const uint32_t sbase = smem_u32(smem);
    // stage s: A at sbase + s*STAGE*4, B at +BM*SSTR*4
    const uint32_t* srcs[4] = {g_f1t, g_f2t, g_n1t, g_n2t};

    // per-thread cp.async coords (4 segments of 16B for A, 4 for B)
    // u = tid + i*256; r = u>>3 (0..127); c4 = u&7 (0..7)
    auto load_chunk = [&](int kc, int stage) {
        const uint32_t* A = srcs[kc >> 2];
        const int colb = (kc & 3) * BK;
        const uint32_t aB = sbase + stage * STAGE_U32 * 4;
        const uint32_t bB = aB + BM * SSTR * 4;
        #pragma unroll
        for (int i = 0; i < 4; i++) {
            int u  = tid + i * 256;
            int r  = u >> 3;
            int c4 = u & 7;
            int gr = block_row + r;
            if (gr >= NNODES) gr = NNODES - 1;    // rows masked at store
            cp_async16(aB + r * (SSTR * 4) + c4 * 16,
                       A + (size_t)gr * DIM + colb + c4 * 4);
            cp_async16(bB + r * (SSTR * 4) + c4 * 16,
                       g_WT + (size_t)r * KTOT + kc * BK + c4 * 4);
        }
    };

    float acc[4][4][4];
    #pragma unroll
    for (int mt = 0; mt < 4; mt++)
        #pragma unroll
        for (int nt = 0; nt < 4; nt++)
            #pragma unroll
            for (int i = 0; i < 4; i++)
                acc[mt][nt][i] = 0.f;

    // prologue
    load_chunk(0, 0);
    CP_COMMIT();

    #pragma unroll 1
    for (int kc = 0; kc < KTOT / BK; kc++) {      // 16 chunks
        CP_WAIT0();
        __syncthreads();                           // buf kc&1 full; prev mma done
        if (kc + 1 < KTOT / BK) load_chunk(kc + 1, (kc + 1) & 1);
        CP_COMMIT();

        const uint32_t aB = sbase + (kc & 1) * STAGE_U32 * 4;
        const uint32_t bB = aB + BM * SSTR * 4;
        const uint32_t* sA = reinterpret_cast<const uint32_t*>(smem) + (kc & 1) * STAGE_U32;
        const uint32_t* sB = sA + BM * SSTR;
        (void)aB; (void)bB;

        #pragma unroll
        for (int ks = 0; ks < 4; ks++) {
            const int ko = ks * 8;
            uint32_t af[4][4];
            #pragma unroll
            for (int mt = 0; mt < 4; mt++) {
                int row = warp_m + mt * 16 + gid;
                af[mt][0] = sA[row * SSTR + ko + tig];
                af[mt][1] = sA[(row + 8) * SSTR + ko + tig];
                af[mt][2] = sA[row * SSTR + ko + tig + 4];
                af[mt][3] = sA[(row + 8) * SSTR + ko + tig + 4];
            }
            uint32_t bf[4][2];
            #pragma unroll
            for (int nt = 0; nt < 4; nt++) {
                int col = warp_n + nt * 8 + gid;
                bf[nt][0] = sB[col * SSTR + ko + tig];
                bf[nt][1] = sB[col * SSTR + ko + tig + 4];
            }
            #pragma unroll
            for (int mt = 0; mt < 4; mt++)
                #pragma unroll
                for (int nt = 0; nt < 4; nt++)
                    mma_tf32(acc[mt][nt], af[mt], bf[nt]);
        }
        __syncthreads();                           // done reading buf kc&1
    }

    // ---- epilogue: tanh + store ----
    #pragma unroll
    for (int mt = 0; mt < 4; mt++) {
        #pragma unroll
        for (int half = 0; half < 2; half++) {
            int gr = block_row + warp_m + mt * 16 + gid + half * 8;
            if (gr < NNODES) {
                #pragma unroll
                for (int nt = 0; nt < 4; nt++) {
                    float2 v;
                    v.x = tanhf(acc[mt][nt][half * 2 + 0]);
                    v.y = tanhf(acc[mt][nt][half * 2 + 1]);
                    *reinterpret_cast<float2*>(
                        out + (size_t)gr * DOUT + warp_n + nt * 8 + tig * 2) = v;
                }
            }
        }
    }
}

// ---------------------------------------------------------------------------
extern "C" void kernel_launch(void* const* d_in, const int* in_sizes, int n_in,
                              void* d_out, int out_size) {
    const float* node_fea1 = (const float*)d_in[0];
    const float* node_fea2 = (const float*)d_in[1];
    const int*   neigh1    = (const int*)  d_in[2];
    const int*   neigh2    = (const int*)  d_in[3];
    const float* weight    = (const float*)d_in[4];
    float*       out       = (float*)d_out;

    prep_kernel<<<NNODES / 8, 256>>>(node_fea1, node_fea2, neigh1, neigh2, weight);

    const int dyn_smem = 2 * STAGE_U32 * 4;   // 73728 B
    static bool attr_set = false;
    if (!attr_set) {
        cudaFuncSetAttribute(gemm_mma_kernel,
                             cudaFuncAttributeMaxDynamicSharedMemorySize, dyn_smem);
        attr_set = true;
    }
    gemm_mma_kernel<<<(NNODES + BM - 1) / BM, 256, dyn_smem>>>(out);
}